// round 11
// baseline (speedup 1.0000x reference)
#include <cuda_runtime.h>
#include <cuda_bf16.h>

// Problem constants
#define TT 512
#define BB 64
#define DD 1024
#define HH 1024
#define NBLK 128
#define NTHR 512

typedef unsigned long long ull;

// SMEM layout (floats)
#define SM_W      32768                 // wsm [1024][32]                   [0,32768)
#define SM_HST    32768                 // hst: 16 warps x 512 u64          [32768,49152)
#define SM_RED    49152                 // red: 16 slices x 256 u64         [49152,57344)
#define SM_TOT_F  57344
#define SM_TOT_B  (SM_TOT_F * 4)        // 229376 B (< 232448 max dynamic)

// Group-barrier slots: 4 groups x 32 blocks, padded to 32 B
__device__ unsigned g_arr[4 * 32 * 8];

// ---------------------------------------------------------------------------
// f32x2 helpers
// ---------------------------------------------------------------------------
__device__ __forceinline__ ull fma2(ull a, ull b, ull c) {
    ull d;
    asm("fma.rn.f32x2 %0, %1, %2, %3;" : "=l"(d) : "l"(a), "l"(b), "l"(c));
    return d;
}
__device__ __forceinline__ ull add2(ull a, ull b) {
    ull d;
    asm("add.rn.f32x2 %0, %1, %2;" : "=l"(d) : "l"(a), "l"(b));
    return d;
}
__device__ __forceinline__ ull pack2(float x, float y) {
    ull d; asm("mov.b64 %0, {%1, %2};" : "=l"(d) : "f"(x), "f"(y)); return d;
}
__device__ __forceinline__ void unpack2(ull v, float& x, float& y) {
    asm("mov.b64 {%0, %1}, %2;" : "=f"(x), "=f"(y) : "l"(v));
}

// ---------------------------------------------------------------------------
// Kernel 1: xproj = inputs @ W_xh + b (FFMA2). Block (0,0) zeroes flags.
// ---------------------------------------------------------------------------
__global__ __launch_bounds__(256) void xproj_kernel(
    const float* __restrict__ A,      // [32768, 1024]
    const float* __restrict__ W,      // [1024, 1024]
    const float* __restrict__ bias,   // [1024]
    float* __restrict__ out)          // [32768, 1024]
{
    __shared__ float As[16][128];
    __shared__ float Bs[16][64];

    const int bm  = blockIdx.y * 128;
    const int bn  = blockIdx.x * 64;
    const int tid = threadIdx.x;
    const int tx  = tid & 15;
    const int ty  = tid >> 4;

    if (blockIdx.x == 0 && blockIdx.y == 0) {
        for (int i = tid; i < 4 * 32 * 8; i += 256) g_arr[i] = 0u;
    }

    ull acc[4][4];
#pragma unroll
    for (int p = 0; p < 4; p++)
#pragma unroll
        for (int j = 0; j < 4; j++) acc[p][j] = 0ull;

    const int r_ld  = tid >> 1;
    const int kq_ld = (tid & 1) * 2;
    const int kk_ld = tid >> 4;
    const int cq_ld = tid & 15;

    for (int k0 = 0; k0 < DD; k0 += 16) {
#pragma unroll
        for (int i = 0; i < 2; i++) {
            float4 v = *(const float4*)&A[(size_t)(bm + r_ld) * DD + k0 + (kq_ld + i) * 4];
            As[(kq_ld + i) * 4 + 0][r_ld] = v.x;
            As[(kq_ld + i) * 4 + 1][r_ld] = v.y;
            As[(kq_ld + i) * 4 + 2][r_ld] = v.z;
            As[(kq_ld + i) * 4 + 3][r_ld] = v.w;
        }
        {
            float4 v = *(const float4*)&W[(size_t)(k0 + kk_ld) * HH + bn + cq_ld * 4];
            *(float4*)&Bs[kk_ld][cq_ld * 4] = v;
        }
        __syncthreads();

#pragma unroll
        for (int kk = 0; kk < 16; kk++) {
            ulonglong2 a0 = *(const ulonglong2*)&As[kk][ty * 8];
            ulonglong2 a1 = *(const ulonglong2*)&As[kk][ty * 8 + 4];
            float4 bq = *(const float4*)&Bs[kk][tx * 4];
            ull b0 = pack2(bq.x, bq.x);
            ull b1 = pack2(bq.y, bq.y);
            ull b2 = pack2(bq.z, bq.z);
            ull b3 = pack2(bq.w, bq.w);
            ull av[4] = {a0.x, a0.y, a1.x, a1.y};
#pragma unroll
            for (int p = 0; p < 4; p++) {
                acc[p][0] = fma2(av[p], b0, acc[p][0]);
                acc[p][1] = fma2(av[p], b1, acc[p][1]);
                acc[p][2] = fma2(av[p], b2, acc[p][2]);
                acc[p][3] = fma2(av[p], b3, acc[p][3]);
            }
        }
        __syncthreads();
    }

    float4 bv;
    bv.x = bias[bn + tx * 4 + 0];
    bv.y = bias[bn + tx * 4 + 1];
    bv.z = bias[bn + tx * 4 + 2];
    bv.w = bias[bn + tx * 4 + 3];
#pragma unroll
    for (int p = 0; p < 4; p++) {
        float lo0, hi0, lo1, hi1, lo2, hi2, lo3, hi3;
        unpack2(acc[p][0], lo0, hi0);
        unpack2(acc[p][1], lo1, hi1);
        unpack2(acc[p][2], lo2, hi2);
        unpack2(acc[p][3], lo3, hi3);
        int row0 = bm + ty * 8 + 2 * p;
        float4 o0; o0.x = lo0 + bv.x; o0.y = lo1 + bv.y; o0.z = lo2 + bv.z; o0.w = lo3 + bv.w;
        float4 o1; o1.x = hi0 + bv.x; o1.y = hi1 + bv.y; o1.z = hi2 + bv.z; o1.w = hi3 + bv.w;
        *(float4*)&out[(size_t)row0 * HH + bn + tx * 4] = o0;
        *(float4*)&out[(size_t)(row0 + 1) * HH + bn + tx * 4] = o1;
    }
}

// ---------------------------------------------------------------------------
// Kernel 2: persistent scan, 512 threads (16 warps). Warp wid = K slice of 64.
// Block (rq,ct): rows rq*16..+15, cols ct*32..+31. Each warp computes the
// FULL 16x32 tile over its 64-k slice (thread = 8 rows x 2 cols).
// Staging: single-shot, warp-private, row pairs (j,j+4) packed u64,
// 16B slots swizzled by (k>>2)&3. Reduction: packed f32x2, 16-way.
// ---------------------------------------------------------------------------
__global__ __launch_bounds__(NTHR, 1) void scan_kernel(
    const float* __restrict__ state,   // [64, 1024]
    const float* __restrict__ Whh,     // [1024, 1024]
    float* __restrict__ out,           // d_out
    int write_final)
{
    extern __shared__ float sm[];
    float* wsm    = sm;                        // [1024][32]
    ull*   hstAll = (ull*)(sm + SM_HST);       // 16 warps x 512 u64
    ull*   redu   = (ull*)(sm + SM_RED);       // 16 x 256 u64

    const int bid = blockIdx.x;
    const int tid = threadIdx.x;
    const int rq  = bid >> 5;
    const int ct  = bid & 31;

    const int lane = tid & 31;
    const int wid  = tid >> 5;         // K slice s: k in [s*64, s*64+64)

    const int cg  = lane & 15;         // colpair: cols 2cg, 2cg+1
    const int rg2 = lane >> 4;         // row octet: rows rg2*8 .. +7

    // W slice: wsm[k*32 + c]
    for (int i = tid; i < 1024 * 32; i += NTHR)
        wsm[i] = Whh[(size_t)(i >> 5) * HH + ct * 32 + (i & 31)];

    const int R0 = rq * 16;
    // staging lane decomposition: k4 = float4 index along k (16 per slice)
    const int k4 = lane & 15;          // k = k4*4 + e
    const int r0 = lane >> 4;          // 0..1 (row parity)
    const int swq = k4 & 3;            // writer slot XOR key = (k>>2)&3
    ull* hw = hstAll + wid * 512;

    // 8 staged rows for this lane: pairs (j, j+4), j in {r0, r0+2}, octets 0,1
    const int rows[8] = {r0, r0 + 4, r0 + 2, r0 + 6,
                         r0 + 8, r0 + 12, r0 + 10, r0 + 14};
    // writer slot offsets (u64 units) for the 4 pairs, within each k's 8-u64 region
    const int wslot[4] = {(0 ^ swq) * 2 + r0, (1 ^ swq) * 2 + r0,
                          (2 ^ swq) * 2 + r0, (3 ^ swq) * 2 + r0};

    // reader slot offsets (m = (k>>2)&3)
    int offA[4], offB[4];
#pragma unroll
    for (int m = 0; m < 4; m++) {
        offA[m] = ((rg2 * 2) ^ m) * 2;
        offB[m] = ((rg2 * 2 + 1) ^ m) * 2;
    }

    // phase-2 mapping: threads 0..255 each own one row-pair/col output
    const int p   = tid;               // valid when tid < 256
    const int pc  = p & 31;
    const int pr  = p >> 5;            // 0..7
    const int po8 = pr >> 2;           // octet
    const int pj  = pr & 3;
    const int gA  = (R0 + po8 * 8 + pj) * HH + ct * 32 + pc;
    const int gB  = gA + 4 * HH;

    unsigned* myslot    = &g_arr[(rq * 32 + ct) * 8];
    const unsigned* pof = &g_arr[(rq * 32 + lane) * 8];

    __syncthreads();

    float xpA = 0.f, xpB = 0.f;
    if (tid < 256) { xpA = out[gA]; xpB = out[gB]; }

    for (int t = 0; t < TT; t++) {
        const float* hsrc = (t == 0) ? state : (out + (size_t)(t - 1) * BB * HH);
        float* xp = out + (size_t)t * BB * HH;

        // ---- load this warp's h slice: 8 rows x 4 k per lane (MLP=8) ----
        float4 v[8];
        {
            const float* base = hsrc + (size_t)R0 * HH + wid * 64 + k4 * 4;
#pragma unroll
            for (int i = 0; i < 8; i++)
                v[i] = __ldcg((const float4*)(base + (size_t)rows[i] * HH));
        }
        // ---- stage: pack row pairs as f32x2, swizzled slots ----
        {
            float e0[8] = {v[0].x, v[1].x, v[2].x, v[3].x, v[4].x, v[5].x, v[6].x, v[7].x};
            float e1[8] = {v[0].y, v[1].y, v[2].y, v[3].y, v[4].y, v[5].y, v[6].y, v[7].y};
            float e2[8] = {v[0].z, v[1].z, v[2].z, v[3].z, v[4].z, v[5].z, v[6].z, v[7].z};
            float e3[8] = {v[0].w, v[1].w, v[2].w, v[3].w, v[4].w, v[5].w, v[6].w, v[7].w};
            ull* d0 = hw + (k4 * 4 + 0) * 8;
            ull* d1 = hw + (k4 * 4 + 1) * 8;
            ull* d2 = hw + (k4 * 4 + 2) * 8;
            ull* d3 = hw + (k4 * 4 + 3) * 8;
#pragma unroll
            for (int q = 0; q < 4; q++) {
                d0[wslot[q]] = pack2(e0[2 * q], e0[2 * q + 1]);
                d1[wslot[q]] = pack2(e1[2 * q], e1[2 * q + 1]);
                d2[wslot[q]] = pack2(e2[2 * q], e2[2 * q + 1]);
                d3[wslot[q]] = pack2(e3[2 * q], e3[2 * q + 1]);
            }
        }
        __syncwarp();

        // ---- compute 64 k straight: per k 2 LDS.128 + 1 LDS.64 + 8 FFMA2 ----
        ull acc00 = 0, acc01 = 0, acc02 = 0, acc03 = 0;
        ull acc10 = 0, acc11 = 0, acc12 = 0, acc13 = 0;
        {
            const float* wb = &wsm[(wid * 64) * 32 + 2 * cg];
#pragma unroll 2
            for (int kh = 0; kh < 2; kh++) {
#pragma unroll
                for (int kk = 0; kk < 32; kk++) {
                    const int k = kh * 32 + kk;
                    const int m = (k >> 2) & 3;
                    ulonglong2 hA = *(const ulonglong2*)(hw + k * 8 + offA[m]);
                    ulonglong2 hB = *(const ulonglong2*)(hw + k * 8 + offB[m]);
                    float2 wp = *(const float2*)(wb + k * 32);
                    ull w0 = pack2(wp.x, wp.x);
                    ull w1 = pack2(wp.y, wp.y);
                    acc00 = fma2(hA.x, w0, acc00);
                    acc01 = fma2(hA.y, w0, acc01);
                    acc02 = fma2(hB.x, w0, acc02);
                    acc03 = fma2(hB.y, w0, acc03);
                    acc10 = fma2(hA.x, w1, acc10);
                    acc11 = fma2(hA.y, w1, acc11);
                    acc12 = fma2(hB.x, w1, acc12);
                    acc13 = fma2(hB.y, w1, acc13);
                }
            }
        }

        // ---- packed partials -> redu[wid][pairrow*32 + col] ----
        {
            ull* rb = redu + wid * 256;
            rb[(rg2 * 4 + 0) * 32 + 2 * cg + 0] = acc00;
            rb[(rg2 * 4 + 1) * 32 + 2 * cg + 0] = acc01;
            rb[(rg2 * 4 + 2) * 32 + 2 * cg + 0] = acc02;
            rb[(rg2 * 4 + 3) * 32 + 2 * cg + 0] = acc03;
            rb[(rg2 * 4 + 0) * 32 + 2 * cg + 1] = acc10;
            rb[(rg2 * 4 + 1) * 32 + 2 * cg + 1] = acc11;
            rb[(rg2 * 4 + 2) * 32 + 2 * cg + 1] = acc12;
            rb[(rg2 * 4 + 3) * 32 + 2 * cg + 1] = acc13;
        }
        __syncthreads();

        // ---- phase 2: 16-way packed sum + xp, tanh, write h_t ----
        if (tid < 256) {
            ull s01 = add2(redu[p],        redu[256 + p]);
            ull s23 = add2(redu[512 + p],  redu[768 + p]);
            ull s45 = add2(redu[1024 + p], redu[1280 + p]);
            ull s67 = add2(redu[1536 + p], redu[1792 + p]);
            ull s89 = add2(redu[2048 + p], redu[2304 + p]);
            ull sab = add2(redu[2560 + p], redu[2816 + p]);
            ull scd = add2(redu[3072 + p], redu[3328 + p]);
            ull sef = add2(redu[3584 + p], redu[3840 + p]);
            ull s = add2(add2(add2(s01, s23), add2(s45, s67)),
                         add2(add2(s89, sab), add2(scd, sef)));
            s = add2(s, pack2(xpA, xpB));
            float aA, aB;
            unpack2(s, aA, aB);
            float h0 = tanhf(aA);
            float h1 = tanhf(aB);
            xp[gA] = h0;
            xp[gB] = h1;
            if (write_final && t == TT - 1) {
                out[(size_t)TT * BB * HH + gA] = h0;
                out[(size_t)TT * BB * HH + gB] = h1;
            }
        }

        if (t < TT - 1) {
            __syncthreads();   // all h_t STGs done (and red reads complete)
            if (tid == 0)
                asm volatile("st.release.gpu.global.b32 [%0], %1;"
                             :: "l"(myslot), "r"((unsigned)(t + 1)));
            if (tid < 256) {   // prefetch next xp during wait
                xpA = xp[BB * HH + gA];
                xpB = xp[BB * HH + gB];
            }
            if (wid == 0) {
                unsigned vv;
                do {
                    asm volatile("ld.acquire.gpu.global.b32 %0, [%1];"
                                 : "=r"(vv) : "l"(pof));
                } while (!__all_sync(0xffffffffu, vv > (unsigned)t));
            }
            __syncthreads();
        }
    }
}

// ---------------------------------------------------------------------------
extern "C" void kernel_launch(void* const* d_in, const int* in_sizes, int n_in,
                              void* d_out, int out_size) {
    const float* inputs = (const float*)d_in[0];   // [T,B,D]
    const float* state  = (const float*)d_in[1];   // [B,H]
    const float* W_xh   = (const float*)d_in[2];   // [D,H]
    const float* W_hh   = (const float*)d_in[3];   // [H,H]
    const float* b_h    = (const float*)d_in[4];   // [H]
    float* out = (float*)d_out;

    int write_final = (out_size >= TT * BB * HH + BB * HH) ? 1 : 0;

    static int smem_set = 0;
    if (!smem_set) {
        cudaFuncSetAttribute(scan_kernel,
                             cudaFuncAttributeMaxDynamicSharedMemorySize,
                             SM_TOT_B);
        smem_set = 1;
    }

    dim3 g1(HH / 64, (TT * BB) / 128);
    xproj_kernel<<<g1, 256>>>(inputs, W_xh, b_h, out);

    scan_kernel<<<NBLK, NTHR, SM_TOT_B>>>(state, W_hh, out, write_final);
}

// round 14
// speedup vs baseline: 1.0190x; 1.0190x over previous
#include <cuda_runtime.h>
#include <cuda_bf16.h>

// Problem constants
#define TT 512
#define BB 64
#define DD 1024
#define HH 1024
#define NBLK 128
#define NTHR 512

typedef unsigned long long ull;

// SMEM layout (floats)
#define SM_W      32768                 // wsm [1024][32]                   [0,32768)
#define SM_HST    32768                 // hst: 16 warps x 512 u64          [32768,49152)
#define SM_RED    49152                 // red: 16 slices x 256 u64         [49152,57344)
#define SM_TOT_F  57344
#define SM_TOT_B  (SM_TOT_F * 4)        // 229376 B (< 232448 max dynamic)

// Group-barrier slots: 4 groups x 32 blocks, padded to 32 B
__device__ unsigned g_arr[4 * 32 * 8];

// ---------------------------------------------------------------------------
// f32x2 helpers
// ---------------------------------------------------------------------------
__device__ __forceinline__ ull fma2(ull a, ull b, ull c) {
    ull d;
    asm("fma.rn.f32x2 %0, %1, %2, %3;" : "=l"(d) : "l"(a), "l"(b), "l"(c));
    return d;
}
__device__ __forceinline__ ull add2(ull a, ull b) {
    ull d;
    asm("add.rn.f32x2 %0, %1, %2;" : "=l"(d) : "l"(a), "l"(b));
    return d;
}
__device__ __forceinline__ ull pack2(float x, float y) {
    ull d; asm("mov.b64 %0, {%1, %2};" : "=l"(d) : "f"(x), "f"(y)); return d;
}
__device__ __forceinline__ void unpack2(ull v, float& x, float& y) {
    asm("mov.b64 {%0, %1}, %2;" : "=f"(x), "=f"(y) : "l"(v));
}

// ---------------------------------------------------------------------------
// Kernel 1: xproj = inputs @ W_xh + b (FFMA2). Block (0,0) zeroes flags.
// ---------------------------------------------------------------------------
__global__ __launch_bounds__(256) void xproj_kernel(
    const float* __restrict__ A,      // [32768, 1024]
    const float* __restrict__ W,      // [1024, 1024]
    const float* __restrict__ bias,   // [1024]
    float* __restrict__ out)          // [32768, 1024]
{
    __shared__ float As[16][128];
    __shared__ float Bs[16][64];

    const int bm  = blockIdx.y * 128;
    const int bn  = blockIdx.x * 64;
    const int tid = threadIdx.x;
    const int tx  = tid & 15;
    const int ty  = tid >> 4;

    if (blockIdx.x == 0 && blockIdx.y == 0) {
        for (int i = tid; i < 4 * 32 * 8; i += 256) g_arr[i] = 0u;
    }

    ull acc[4][4];
#pragma unroll
    for (int p = 0; p < 4; p++)
#pragma unroll
        for (int j = 0; j < 4; j++) acc[p][j] = 0ull;

    const int r_ld  = tid >> 1;
    const int kq_ld = (tid & 1) * 2;
    const int kk_ld = tid >> 4;
    const int cq_ld = tid & 15;

    for (int k0 = 0; k0 < DD; k0 += 16) {
#pragma unroll
        for (int i = 0; i < 2; i++) {
            float4 v = *(const float4*)&A[(size_t)(bm + r_ld) * DD + k0 + (kq_ld + i) * 4];
            As[(kq_ld + i) * 4 + 0][r_ld] = v.x;
            As[(kq_ld + i) * 4 + 1][r_ld] = v.y;
            As[(kq_ld + i) * 4 + 2][r_ld] = v.z;
            As[(kq_ld + i) * 4 + 3][r_ld] = v.w;
        }
        {
            float4 v = *(const float4*)&W[(size_t)(k0 + kk_ld) * HH + bn + cq_ld * 4];
            *(float4*)&Bs[kk_ld][cq_ld * 4] = v;
        }
        __syncthreads();

#pragma unroll
        for (int kk = 0; kk < 16; kk++) {
            ulonglong2 a0 = *(const ulonglong2*)&As[kk][ty * 8];
            ulonglong2 a1 = *(const ulonglong2*)&As[kk][ty * 8 + 4];
            float4 bq = *(const float4*)&Bs[kk][tx * 4];
            ull b0 = pack2(bq.x, bq.x);
            ull b1 = pack2(bq.y, bq.y);
            ull b2 = pack2(bq.z, bq.z);
            ull b3 = pack2(bq.w, bq.w);
            ull av[4] = {a0.x, a0.y, a1.x, a1.y};
#pragma unroll
            for (int p = 0; p < 4; p++) {
                acc[p][0] = fma2(av[p], b0, acc[p][0]);
                acc[p][1] = fma2(av[p], b1, acc[p][1]);
                acc[p][2] = fma2(av[p], b2, acc[p][2]);
                acc[p][3] = fma2(av[p], b3, acc[p][3]);
            }
        }
        __syncthreads();
    }

    float4 bv;
    bv.x = bias[bn + tx * 4 + 0];
    bv.y = bias[bn + tx * 4 + 1];
    bv.z = bias[bn + tx * 4 + 2];
    bv.w = bias[bn + tx * 4 + 3];
#pragma unroll
    for (int p = 0; p < 4; p++) {
        float lo0, hi0, lo1, hi1, lo2, hi2, lo3, hi3;
        unpack2(acc[p][0], lo0, hi0);
        unpack2(acc[p][1], lo1, hi1);
        unpack2(acc[p][2], lo2, hi2);
        unpack2(acc[p][3], lo3, hi3);
        int row0 = bm + ty * 8 + 2 * p;
        float4 o0; o0.x = lo0 + bv.x; o0.y = lo1 + bv.y; o0.z = lo2 + bv.z; o0.w = lo3 + bv.w;
        float4 o1; o1.x = hi0 + bv.x; o1.y = hi1 + bv.y; o1.z = hi2 + bv.z; o1.w = hi3 + bv.w;
        *(float4*)&out[(size_t)row0 * HH + bn + tx * 4] = o0;
        *(float4*)&out[(size_t)(row0 + 1) * HH + bn + tx * 4] = o1;
    }
}

// ---------------------------------------------------------------------------
// Kernel 2: persistent scan, 512 threads (16 warps). Warp wid = K slice of 64.
// Block (rq,ct): rows rq*16..+15, cols ct*32..+31. Each warp computes the
// FULL 16x32 tile over its 64-k slice (thread = 8 rows x 2 cols).
// Staging: single-shot, warp-private, pairs packed straight from LDG regs,
// 16B slots swizzled by (k>>2)&3. Reduction: packed f32x2, 16-way.
// ---------------------------------------------------------------------------
__global__ __launch_bounds__(NTHR, 1) void scan_kernel(
    const float* __restrict__ state,   // [64, 1024]
    const float* __restrict__ Whh,     // [1024, 1024]
    float* __restrict__ out,           // d_out
    int write_final)
{
    extern __shared__ float sm[];
    float* wsm    = sm;                        // [1024][32]
    ull*   hstAll = (ull*)(sm + SM_HST);       // 16 warps x 512 u64
    ull*   redu   = (ull*)(sm + SM_RED);       // 16 x 256 u64

    const int bid = blockIdx.x;
    const int tid = threadIdx.x;
    const int rq  = bid >> 5;
    const int ct  = bid & 31;

    const int lane = tid & 31;
    const int wid  = tid >> 5;         // K slice s: k in [s*64, s*64+64)

    const int cg  = lane & 15;         // colpair: cols 2cg, 2cg+1
    const int rg2 = lane >> 4;         // row octet: rows rg2*8 .. +7

    // W slice: wsm[k*32 + c]
    for (int i = tid; i < 1024 * 32; i += NTHR)
        wsm[i] = Whh[(size_t)(i >> 5) * HH + ct * 32 + (i & 31)];

    const int R0 = rq * 16;
    // staging lane decomposition: k4 = float4 index along k (16 per slice)
    const int k4 = lane & 15;          // covers k = k4*4 .. k4*4+3
    const int r0 = lane >> 4;          // 0..1 (row parity)
    const int swq = k4 & 3;            // writer slot XOR key = (k>>2)&3
    ull* hw = hstAll + wid * 512;

    // staged rows, pair q -> logical pair lp = 2q + r0 -> rows (8*(lp>>2)+(lp&3), +4)
    const int rows0 = r0;        // pair 0: rows (r0,    r0+4)
    const int rows1 = r0 + 2;    // pair 1: rows (r0+2,  r0+6)
    const int rows2 = r0 + 8;    // pair 2: rows (r0+8,  r0+12)
    const int rows3 = r0 + 10;   // pair 3: rows (r0+10, r0+14)
    // writer slot offsets (u64 units) within each k's 8-u64 region
    const int ws0 = (0 ^ swq) * 2 + r0;
    const int ws1 = (1 ^ swq) * 2 + r0;
    const int ws2 = (2 ^ swq) * 2 + r0;
    const int ws3 = (3 ^ swq) * 2 + r0;

    // reader slot offsets (m = (k>>2)&3)
    int offA[4], offB[4];
#pragma unroll
    for (int m = 0; m < 4; m++) {
        offA[m] = ((rg2 * 2) ^ m) * 2;
        offB[m] = ((rg2 * 2 + 1) ^ m) * 2;
    }

    // phase-2 mapping: threads 0..255 each own one row-pair/col output
    const int p   = tid;               // valid when tid < 256
    const int pc  = p & 31;
    const int pr  = p >> 5;            // logical pair 0..7
    const int gA  = (R0 + (pr >> 2) * 8 + (pr & 3)) * HH + ct * 32 + pc;
    const int gB  = gA + 4 * HH;

    unsigned* myslot    = &g_arr[(rq * 32 + ct) * 8];
    const unsigned* pof = &g_arr[(rq * 32 + lane) * 8];

    __syncthreads();

    float xpA = 0.f, xpB = 0.f;
    if (tid < 256) { xpA = out[gA]; xpB = out[gB]; }

    for (int t = 0; t < TT; t++) {
        const float* hsrc = (t == 0) ? state : (out + (size_t)(t - 1) * BB * HH);
        float* xp = out + (size_t)t * BB * HH;

        // ---- load + stage this warp's h slice (MLP=8, pairs packed direct) ----
        {
            const float* base = hsrc + (size_t)R0 * HH + wid * 64 + k4 * 4;
            float4 a0 = __ldcg((const float4*)(base + (size_t)(rows0)     * HH));
            float4 a1 = __ldcg((const float4*)(base + (size_t)(rows0 + 4) * HH));
            float4 b0 = __ldcg((const float4*)(base + (size_t)(rows1)     * HH));
            float4 b1 = __ldcg((const float4*)(base + (size_t)(rows1 + 4) * HH));
            float4 c0 = __ldcg((const float4*)(base + (size_t)(rows2)     * HH));
            float4 c1 = __ldcg((const float4*)(base + (size_t)(rows2 + 4) * HH));
            float4 d0 = __ldcg((const float4*)(base + (size_t)(rows3)     * HH));
            float4 d1 = __ldcg((const float4*)(base + (size_t)(rows3 + 4) * HH));

            ull* k0p = hw + (k4 * 4 + 0) * 8;
            ull* k1p = hw + (k4 * 4 + 1) * 8;
            ull* k2p = hw + (k4 * 4 + 2) * 8;
            ull* k3p = hw + (k4 * 4 + 3) * 8;
            k0p[ws0] = pack2(a0.x, a1.x);  k0p[ws1] = pack2(b0.x, b1.x);
            k0p[ws2] = pack2(c0.x, c1.x);  k0p[ws3] = pack2(d0.x, d1.x);
            k1p[ws0] = pack2(a0.y, a1.y);  k1p[ws1] = pack2(b0.y, b1.y);
            k1p[ws2] = pack2(c0.y, c1.y);  k1p[ws3] = pack2(d0.y, d1.y);
            k2p[ws0] = pack2(a0.z, a1.z);  k2p[ws1] = pack2(b0.z, b1.z);
            k2p[ws2] = pack2(c0.z, c1.z);  k2p[ws3] = pack2(d0.z, d1.z);
            k3p[ws0] = pack2(a0.w, a1.w);  k3p[ws1] = pack2(b0.w, b1.w);
            k3p[ws2] = pack2(c0.w, c1.w);  k3p[ws3] = pack2(d0.w, d1.w);
        }
        __syncwarp();

        // ---- compute 64 k straight: per k 2 LDS.128 + 1 LDS.64 + 8 FFMA2 ----
        ull acc00 = 0, acc01 = 0, acc02 = 0, acc03 = 0;
        ull acc10 = 0, acc11 = 0, acc12 = 0, acc13 = 0;
        {
            const float* wb = &wsm[(wid * 64) * 32 + 2 * cg];
#pragma unroll
            for (int k = 0; k < 64; k++) {
                const int m = (k >> 2) & 3;
                ulonglong2 hA = *(const ulonglong2*)(hw + k * 8 + offA[m]);
                ulonglong2 hB = *(const ulonglong2*)(hw + k * 8 + offB[m]);
                float2 wp = *(const float2*)(wb + k * 32);
                ull w0 = pack2(wp.x, wp.x);
                ull w1 = pack2(wp.y, wp.y);
                acc00 = fma2(hA.x, w0, acc00);
                acc01 = fma2(hA.y, w0, acc01);
                acc02 = fma2(hB.x, w0, acc02);
                acc03 = fma2(hB.y, w0, acc03);
                acc10 = fma2(hA.x, w1, acc10);
                acc11 = fma2(hA.y, w1, acc11);
                acc12 = fma2(hB.x, w1, acc12);
                acc13 = fma2(hB.y, w1, acc13);
            }
        }

        // ---- packed partials -> redu[wid][logical_pair*32 + col] ----
        {
            ull* rb = redu + wid * 256;
            rb[(rg2 * 4 + 0) * 32 + 2 * cg + 0] = acc00;
            rb[(rg2 * 4 + 1) * 32 + 2 * cg + 0] = acc01;
            rb[(rg2 * 4 + 2) * 32 + 2 * cg + 0] = acc02;
            rb[(rg2 * 4 + 3) * 32 + 2 * cg + 0] = acc03;
            rb[(rg2 * 4 + 0) * 32 + 2 * cg + 1] = acc10;
            rb[(rg2 * 4 + 1) * 32 + 2 * cg + 1] = acc11;
            rb[(rg2 * 4 + 2) * 32 + 2 * cg + 1] = acc12;
            rb[(rg2 * 4 + 3) * 32 + 2 * cg + 1] = acc13;
        }
        __syncthreads();

        // ---- phase 2: 16-way packed sum + xp, tanh, write h_t ----
        if (tid < 256) {
            ull s01 = add2(redu[p],        redu[256 + p]);
            ull s23 = add2(redu[512 + p],  redu[768 + p]);
            ull s45 = add2(redu[1024 + p], redu[1280 + p]);
            ull s67 = add2(redu[1536 + p], redu[1792 + p]);
            ull s89 = add2(redu[2048 + p], redu[2304 + p]);
            ull sab = add2(redu[2560 + p], redu[2816 + p]);
            ull scd = add2(redu[3072 + p], redu[3328 + p]);
            ull sef = add2(redu[3584 + p], redu[3840 + p]);
            ull s = add2(add2(add2(s01, s23), add2(s45, s67)),
                         add2(add2(s89, sab), add2(scd, sef)));
            s = add2(s, pack2(xpA, xpB));
            float aA, aB;
            unpack2(s, aA, aB);
            float h0 = tanhf(aA);
            float h1 = tanhf(aB);
            xp[gA] = h0;
            xp[gB] = h1;
            if (write_final && t == TT - 1) {
                out[(size_t)TT * BB * HH + gA] = h0;
                out[(size_t)TT * BB * HH + gB] = h1;
            }
        }

        if (t < TT - 1) {
            __syncthreads();   // all h_t STGs done (and redu reads complete)
            if (tid == 0)
                asm volatile("st.release.gpu.global.b32 [%0], %1;"
                             :: "l"(myslot), "r"((unsigned)(t + 1)));
            if (tid < 256) {   // prefetch next xp during wait
                xpA = xp[BB * HH + gA];
                xpB = xp[BB * HH + gB];
            }
            if (wid == 0) {
                unsigned vv;
                do {
                    asm volatile("ld.acquire.gpu.global.b32 %0, [%1];"
                                 : "=r"(vv) : "l"(pof));
                } while (!__all_sync(0xffffffffu, vv > (unsigned)t));
            }
            __syncthreads();
        }
    }
}

// ---------------------------------------------------------------------------
extern "C" void kernel_launch(void* const* d_in, const int* in_sizes, int n_in,
                              void* d_out, int out_size) {
    const float* inputs = (const float*)d_in[0];   // [T,B,D]
    const float* state  = (const float*)d_in[1];   // [B,H]
    const float* W_xh   = (const float*)d_in[2];   // [D,H]
    const float* W_hh   = (const float*)d_in[3];   // [H,H]
    const float* b_h    = (const float*)d_in[4];   // [H]
    float* out = (float*)d_out;

    int write_final = (out_size >= TT * BB * HH + BB * HH) ? 1 : 0;

    static int smem_set = 0;
    if (!smem_set) {
        cudaFuncSetAttribute(scan_kernel,
                             cudaFuncAttributeMaxDynamicSharedMemorySize,
                             SM_TOT_B);
        smem_set = 1;
    }

    dim3 g1(HH / 64, (TT * BB) / 128);
    xproj_kernel<<<g1, 256>>>(inputs, W_xh, b_h, out);

    scan_kernel<<<NBLK, NTHR, SM_TOT_B>>>(state, W_hh, out, write_final);
}

// round 16
// speedup vs baseline: 1.0201x; 1.0011x over previous
#include <cuda_runtime.h>
#include <cuda_bf16.h>

// Problem constants
#define TT 512
#define BB 64
#define DD 1024
#define HH 1024
#define NBLK 128
#define NTHR 512

typedef unsigned long long ull;

// SMEM layout (floats)
#define SM_W      32768                 // wsm [1024][32]                   [0,32768)
#define SM_HST    32768                 // hst: 16 warps x 512 u64          [32768,49152)
#define SM_RED    49152                 // red: 16 slices x 256 u64         [49152,57344)
#define SM_TOT_F  57344
#define SM_TOT_B  (SM_TOT_F * 4)        // 229376 B (< 232448 max dynamic)

// Group-barrier slots: 4 groups x 32 blocks, padded to 32 B
__device__ unsigned g_arr[4 * 32 * 8];

// ---------------------------------------------------------------------------
// f32x2 helpers
// ---------------------------------------------------------------------------
__device__ __forceinline__ ull fma2(ull a, ull b, ull c) {
    ull d;
    asm("fma.rn.f32x2 %0, %1, %2, %3;" : "=l"(d) : "l"(a), "l"(b), "l"(c));
    return d;
}
__device__ __forceinline__ ull add2(ull a, ull b) {
    ull d;
    asm("add.rn.f32x2 %0, %1, %2;" : "=l"(d) : "l"(a), "l"(b));
    return d;
}
__device__ __forceinline__ ull pack2(float x, float y) {
    ull d; asm("mov.b64 %0, {%1, %2};" : "=l"(d) : "f"(x), "f"(y)); return d;
}
__device__ __forceinline__ void unpack2(ull v, float& x, float& y) {
    asm("mov.b64 {%0, %1}, %2;" : "=f"(x), "=f"(y) : "l"(v));
}

// ---------------------------------------------------------------------------
// Kernel 1: xproj = inputs @ W_xh + b (FFMA2). Block (0,0) zeroes flags.
// ---------------------------------------------------------------------------
__global__ __launch_bounds__(256) void xproj_kernel(
    const float* __restrict__ A,      // [32768, 1024]
    const float* __restrict__ W,      // [1024, 1024]
    const float* __restrict__ bias,   // [1024]
    float* __restrict__ out)          // [32768, 1024]
{
    __shared__ float As[16][128];
    __shared__ float Bs[16][64];

    const int bm  = blockIdx.y * 128;
    const int bn  = blockIdx.x * 64;
    const int tid = threadIdx.x;
    const int tx  = tid & 15;
    const int ty  = tid >> 4;

    if (blockIdx.x == 0 && blockIdx.y == 0) {
        for (int i = tid; i < 4 * 32 * 8; i += 256) g_arr[i] = 0u;
    }

    ull acc[4][4];
#pragma unroll
    for (int p = 0; p < 4; p++)
#pragma unroll
        for (int j = 0; j < 4; j++) acc[p][j] = 0ull;

    const int r_ld  = tid >> 1;
    const int kq_ld = (tid & 1) * 2;
    const int kk_ld = tid >> 4;
    const int cq_ld = tid & 15;

    for (int k0 = 0; k0 < DD; k0 += 16) {
#pragma unroll
        for (int i = 0; i < 2; i++) {
            float4 v = *(const float4*)&A[(size_t)(bm + r_ld) * DD + k0 + (kq_ld + i) * 4];
            As[(kq_ld + i) * 4 + 0][r_ld] = v.x;
            As[(kq_ld + i) * 4 + 1][r_ld] = v.y;
            As[(kq_ld + i) * 4 + 2][r_ld] = v.z;
            As[(kq_ld + i) * 4 + 3][r_ld] = v.w;
        }
        {
            float4 v = *(const float4*)&W[(size_t)(k0 + kk_ld) * HH + bn + cq_ld * 4];
            *(float4*)&Bs[kk_ld][cq_ld * 4] = v;
        }
        __syncthreads();

#pragma unroll
        for (int kk = 0; kk < 16; kk++) {
            ulonglong2 a0 = *(const ulonglong2*)&As[kk][ty * 8];
            ulonglong2 a1 = *(const ulonglong2*)&As[kk][ty * 8 + 4];
            float4 bq = *(const float4*)&Bs[kk][tx * 4];
            ull b0 = pack2(bq.x, bq.x);
            ull b1 = pack2(bq.y, bq.y);
            ull b2 = pack2(bq.z, bq.z);
            ull b3 = pack2(bq.w, bq.w);
            ull av[4] = {a0.x, a0.y, a1.x, a1.y};
#pragma unroll
            for (int p = 0; p < 4; p++) {
                acc[p][0] = fma2(av[p], b0, acc[p][0]);
                acc[p][1] = fma2(av[p], b1, acc[p][1]);
                acc[p][2] = fma2(av[p], b2, acc[p][2]);
                acc[p][3] = fma2(av[p], b3, acc[p][3]);
            }
        }
        __syncthreads();
    }

    float4 bv;
    bv.x = bias[bn + tx * 4 + 0];
    bv.y = bias[bn + tx * 4 + 1];
    bv.z = bias[bn + tx * 4 + 2];
    bv.w = bias[bn + tx * 4 + 3];
#pragma unroll
    for (int p = 0; p < 4; p++) {
        float lo0, hi0, lo1, hi1, lo2, hi2, lo3, hi3;
        unpack2(acc[p][0], lo0, hi0);
        unpack2(acc[p][1], lo1, hi1);
        unpack2(acc[p][2], lo2, hi2);
        unpack2(acc[p][3], lo3, hi3);
        int row0 = bm + ty * 8 + 2 * p;
        float4 o0; o0.x = lo0 + bv.x; o0.y = lo1 + bv.y; o0.z = lo2 + bv.z; o0.w = lo3 + bv.w;
        float4 o1; o1.x = hi0 + bv.x; o1.y = hi1 + bv.y; o1.z = hi2 + bv.z; o1.w = hi3 + bv.w;
        *(float4*)&out[(size_t)row0 * HH + bn + tx * 4] = o0;
        *(float4*)&out[(size_t)(row0 + 1) * HH + bn + tx * 4] = o1;
    }
}

// ---------------------------------------------------------------------------
// Kernel 2: persistent scan, 512 threads (16 warps). Warp wid = K slice of 64.
// Block (rq,ct): rows rq*16..+15, cols ct*32..+31. Each warp computes the
// FULL 16x32 tile over its 64-k slice (thread = 8 rows x 2 cols).
// Staging: single-shot, warp-private, pairs packed straight from LDG regs,
// 16B slots swizzled by (k>>2)&3. Reduction: packed f32x2, 16-way.
// ---------------------------------------------------------------------------
__global__ __launch_bounds__(NTHR, 1) void scan_kernel(
    const float* __restrict__ state,   // [64, 1024]
    const float* __restrict__ Whh,     // [1024, 1024]
    float* __restrict__ out,           // d_out
    int write_final)
{
    extern __shared__ float sm[];
    float* wsm    = sm;                        // [1024][32]
    ull*   hstAll = (ull*)(sm + SM_HST);       // 16 warps x 512 u64
    ull*   redu   = (ull*)(sm + SM_RED);       // 16 x 256 u64

    const int bid = blockIdx.x;
    const int tid = threadIdx.x;
    const int rq  = bid >> 5;
    const int ct  = bid & 31;

    const int lane = tid & 31;
    const int wid  = tid >> 5;         // K slice s: k in [s*64, s*64+64)

    const int cg  = lane & 15;         // colpair: cols 2cg, 2cg+1
    const int rg2 = lane >> 4;         // row octet: rows rg2*8 .. +7

    // W slice: wsm[k*32 + c]
    for (int i = tid; i < 1024 * 32; i += NTHR)
        wsm[i] = Whh[(size_t)(i >> 5) * HH + ct * 32 + (i & 31)];

    const int R0 = rq * 16;
    // staging lane decomposition: k4 = float4 index along k (16 per slice)
    const int k4 = lane & 15;          // covers k = k4*4 .. k4*4+3
    const int r0 = lane >> 4;          // 0..1 (row parity)
    const int swq = k4 & 3;            // writer slot XOR key = (k>>2)&3
    ull* hw = hstAll + wid * 512;

    // staged rows, pair q -> logical pair lp = 2q + r0 -> rows (8*(lp>>2)+(lp&3), +4)
    const int rows0 = r0;        // pair 0: rows (r0,    r0+4)
    const int rows1 = r0 + 2;    // pair 1: rows (r0+2,  r0+6)
    const int rows2 = r0 + 8;    // pair 2: rows (r0+8,  r0+12)
    const int rows3 = r0 + 10;   // pair 3: rows (r0+10, r0+14)
    // writer slot offsets (u64 units) within each k's 8-u64 region
    const int ws0 = (0 ^ swq) * 2 + r0;
    const int ws1 = (1 ^ swq) * 2 + r0;
    const int ws2 = (2 ^ swq) * 2 + r0;
    const int ws3 = (3 ^ swq) * 2 + r0;

    // reader slot offsets (m = (k>>2)&3)
    int offA[4], offB[4];
#pragma unroll
    for (int m = 0; m < 4; m++) {
        offA[m] = ((rg2 * 2) ^ m) * 2;
        offB[m] = ((rg2 * 2 + 1) ^ m) * 2;
    }

    // phase-2 mapping: threads 0..255 each own one row-pair/col output
    const int p   = tid;               // valid when tid < 256
    const int pc  = p & 31;
    const int pr  = p >> 5;            // logical pair 0..7
    const int gA  = (R0 + (pr >> 2) * 8 + (pr & 3)) * HH + ct * 32 + pc;
    const int gB  = gA + 4 * HH;

    unsigned* myslot    = &g_arr[(rq * 32 + ct) * 8];
    const unsigned* pof = &g_arr[(rq * 32 + lane) * 8];

    __syncthreads();

    float xpA = 0.f, xpB = 0.f;
    if (tid < 256) { xpA = out[gA]; xpB = out[gB]; }

    for (int t = 0; t < TT; t++) {
        const float* hsrc = (t == 0) ? state : (out + (size_t)(t - 1) * BB * HH);
        float* xp = out + (size_t)t * BB * HH;

        // ---- load + stage this warp's h slice (MLP=8, pairs packed direct) ----
        {
            const float* base = hsrc + (size_t)R0 * HH + wid * 64 + k4 * 4;
            float4 a0 = __ldcg((const float4*)(base + (size_t)(rows0)     * HH));
            float4 a1 = __ldcg((const float4*)(base + (size_t)(rows0 + 4) * HH));
            float4 b0 = __ldcg((const float4*)(base + (size_t)(rows1)     * HH));
            float4 b1 = __ldcg((const float4*)(base + (size_t)(rows1 + 4) * HH));
            float4 c0 = __ldcg((const float4*)(base + (size_t)(rows2)     * HH));
            float4 c1 = __ldcg((const float4*)(base + (size_t)(rows2 + 4) * HH));
            float4 d0 = __ldcg((const float4*)(base + (size_t)(rows3)     * HH));
            float4 d1 = __ldcg((const float4*)(base + (size_t)(rows3 + 4) * HH));

            ull* k0p = hw + (k4 * 4 + 0) * 8;
            ull* k1p = hw + (k4 * 4 + 1) * 8;
            ull* k2p = hw + (k4 * 4 + 2) * 8;
            ull* k3p = hw + (k4 * 4 + 3) * 8;
            k0p[ws0] = pack2(a0.x, a1.x);  k0p[ws1] = pack2(b0.x, b1.x);
            k0p[ws2] = pack2(c0.x, c1.x);  k0p[ws3] = pack2(d0.x, d1.x);
            k1p[ws0] = pack2(a0.y, a1.y);  k1p[ws1] = pack2(b0.y, b1.y);
            k1p[ws2] = pack2(c0.y, c1.y);  k1p[ws3] = pack2(d0.y, d1.y);
            k2p[ws0] = pack2(a0.z, a1.z);  k2p[ws1] = pack2(b0.z, b1.z);
            k2p[ws2] = pack2(c0.z, c1.z);  k2p[ws3] = pack2(d0.z, d1.z);
            k3p[ws0] = pack2(a0.w, a1.w);  k3p[ws1] = pack2(b0.w, b1.w);
            k3p[ws2] = pack2(c0.w, c1.w);  k3p[ws3] = pack2(d0.w, d1.w);
        }
        __syncwarp();

        // ---- compute 64 k straight: per k 2 LDS.128 + 1 LDS.64 + 8 FFMA2 ----
        ull acc00 = 0, acc01 = 0, acc02 = 0, acc03 = 0;
        ull acc10 = 0, acc11 = 0, acc12 = 0, acc13 = 0;
        {
            const float* wb = &wsm[(wid * 64) * 32 + 2 * cg];
#pragma unroll
            for (int k = 0; k < 64; k++) {
                const int m = (k >> 2) & 3;
                ulonglong2 hA = *(const ulonglong2*)(hw + k * 8 + offA[m]);
                ulonglong2 hB = *(const ulonglong2*)(hw + k * 8 + offB[m]);
                float2 wp = *(const float2*)(wb + k * 32);
                ull w0 = pack2(wp.x, wp.x);
                ull w1 = pack2(wp.y, wp.y);
                acc00 = fma2(hA.x, w0, acc00);
                acc01 = fma2(hA.y, w0, acc01);
                acc02 = fma2(hB.x, w0, acc02);
                acc03 = fma2(hB.y, w0, acc03);
                acc10 = fma2(hA.x, w1, acc10);
                acc11 = fma2(hA.y, w1, acc11);
                acc12 = fma2(hB.x, w1, acc12);
                acc13 = fma2(hB.y, w1, acc13);
            }
        }

        // ---- packed partials -> redu[wid][logical_pair*32 + col] ----
        {
            ull* rb = redu + wid * 256;
            rb[(rg2 * 4 + 0) * 32 + 2 * cg + 0] = acc00;
            rb[(rg2 * 4 + 1) * 32 + 2 * cg + 0] = acc01;
            rb[(rg2 * 4 + 2) * 32 + 2 * cg + 0] = acc02;
            rb[(rg2 * 4 + 3) * 32 + 2 * cg + 0] = acc03;
            rb[(rg2 * 4 + 0) * 32 + 2 * cg + 1] = acc10;
            rb[(rg2 * 4 + 1) * 32 + 2 * cg + 1] = acc11;
            rb[(rg2 * 4 + 2) * 32 + 2 * cg + 1] = acc12;
            rb[(rg2 * 4 + 3) * 32 + 2 * cg + 1] = acc13;
        }
        __syncthreads();

        // ---- phase 2: 16-way packed sum + xp, tanh, write h_t ----
        if (tid < 256) {
            ull s01 = add2(redu[p],        redu[256 + p]);
            ull s23 = add2(redu[512 + p],  redu[768 + p]);
            ull s45 = add2(redu[1024 + p], redu[1280 + p]);
            ull s67 = add2(redu[1536 + p], redu[1792 + p]);
            ull s89 = add2(redu[2048 + p], redu[2304 + p]);
            ull sab = add2(redu[2560 + p], redu[2816 + p]);
            ull scd = add2(redu[3072 + p], redu[3328 + p]);
            ull sef = add2(redu[3584 + p], redu[3840 + p]);
            ull s = add2(add2(add2(s01, s23), add2(s45, s67)),
                         add2(add2(s89, sab), add2(scd, sef)));
            s = add2(s, pack2(xpA, xpB));
            float aA, aB;
            unpack2(s, aA, aB);
            float h0 = tanhf(aA);
            float h1 = tanhf(aB);
            xp[gA] = h0;
            xp[gB] = h1;
            if (write_final && t == TT - 1) {
                out[(size_t)TT * BB * HH + gA] = h0;
                out[(size_t)TT * BB * HH + gB] = h1;
            }
        }

        if (t < TT - 1) {
            __syncthreads();   // all h_t STGs done (and redu reads complete)
            if (tid == 0)
                asm volatile("st.release.gpu.global.b32 [%0], %1;"
                             :: "l"(myslot), "r"((unsigned)(t + 1)));
            if (tid < 256) {   // prefetch next xp during wait
                xpA = xp[BB * HH + gA];
                xpB = xp[BB * HH + gB];
            }
            if (wid == 0) {
                unsigned vv;
                do {
                    asm volatile("ld.acquire.gpu.global.b32 %0, [%1];"
                                 : "=r"(vv) : "l"(pof));
                } while (!__all_sync(0xffffffffu, vv > (unsigned)t));
            }
            __syncthreads();
        }
    }
}

// ---------------------------------------------------------------------------
extern "C" void kernel_launch(void* const* d_in, const int* in_sizes, int n_in,
                              void* d_out, int out_size) {
    const float* inputs = (const float*)d_in[0];   // [T,B,D]
    const float* state  = (const float*)d_in[1];   // [B,H]
    const float* W_xh   = (const float*)d_in[2];   // [D,H]
    const float* W_hh   = (const float*)d_in[3];   // [H,H]
    const float* b_h    = (const float*)d_in[4];   // [H]
    float* out = (float*)d_out;

    int write_final = (out_size >= TT * BB * HH + BB * HH) ? 1 : 0;

    static int smem_set = 0;
    if (!smem_set) {
        cudaFuncSetAttribute(scan_kernel,
                             cudaFuncAttributeMaxDynamicSharedMemorySize,
                             SM_TOT_B);
        smem_set = 1;
    }

    dim3 g1(HH / 64, (TT * BB) / 128);
    xproj_kernel<<<g1, 256>>>(inputs, W_xh, b_h, out);

    scan_kernel<<<NBLK, NTHR, SM_TOT_B>>>(state, W_hh, out, write_final);
}

// round 17
// speedup vs baseline: 1.0626x; 1.0417x over previous
#include <cuda_runtime.h>
#include <cuda_bf16.h>

// Problem constants
#define TT 512
#define BB 64
#define DD 1024
#define HH 1024
#define NBLK 128
#define NTHR 256

typedef unsigned long long ull;

// SMEM layout for scan (floats) — identical to the proven R10 kernel
#define SM_W      32768                 // wsm [1024][32]                 [0,32768)
#define SM_HST    32768                 // hst: 8 warps x 2 buf x 256 u64 [32768,40960)
#define SM_RED    40960                 // red [8][512]                   [40960,45056)
#define SM_TOT_F  45056
#define SM_TOT_B  (SM_TOT_F * 4)        // 180224 B < 227 KB

// Group-barrier slots: 4 groups x 32 blocks, padded to 32 B
__device__ unsigned g_arr[4 * 32 * 8];
// xproj readiness: one counter + one flag per t-pair (256 pairs)
__device__ unsigned g_xpcnt[256];
__device__ unsigned g_xpready[256];

// ---------------------------------------------------------------------------
// f32x2 helpers
// ---------------------------------------------------------------------------
__device__ __forceinline__ ull fma2(ull a, ull b, ull c) {
    ull d;
    asm("fma.rn.f32x2 %0, %1, %2, %3;" : "=l"(d) : "l"(a), "l"(b), "l"(c));
    return d;
}
__device__ __forceinline__ ull pack2(float x, float y) {
    ull d; asm("mov.b64 %0, {%1, %2};" : "=l"(d) : "f"(x), "f"(y)); return d;
}
__device__ __forceinline__ void unpack2(ull v, float& x, float& y) {
    asm("mov.b64 {%0, %1}, %2;" : "=f"(x), "=f"(y) : "l"(v));
}

// ---------------------------------------------------------------------------
// Init: zero all flags/counters (replay-deterministic), runs before fork.
// ---------------------------------------------------------------------------
__global__ void init_kernel() {
    int i = blockIdx.x * blockDim.x + threadIdx.x;
    if (i < 4 * 32 * 8) g_arr[i] = 0u;
    if (i < 256) { g_xpcnt[i] = 0u; g_xpready[i] = 0u; }
}

// ---------------------------------------------------------------------------
// Kernel 1: xproj = inputs @ W_xh + b (FFMA2).
// blockIdx.y = t-pair (rows 128y..128y+127 = timesteps 2y,2y+1).
// Completion: fence + count; 16th block per pair release-sets xpready[pair].
// ---------------------------------------------------------------------------
__global__ __launch_bounds__(256) void xproj_kernel(
    const float* __restrict__ A,      // [32768, 1024]
    const float* __restrict__ W,      // [1024, 1024]
    const float* __restrict__ bias,   // [1024]
    float* __restrict__ out)          // [32768, 1024]
{
    __shared__ float As[16][128];
    __shared__ float Bs[16][64];

    const int bm  = blockIdx.y * 128;
    const int bn  = blockIdx.x * 64;
    const int tid = threadIdx.x;
    const int tx  = tid & 15;
    const int ty  = tid >> 4;

    ull acc[4][4];
#pragma unroll
    for (int p = 0; p < 4; p++)
#pragma unroll
        for (int j = 0; j < 4; j++) acc[p][j] = 0ull;

    const int r_ld  = tid >> 1;
    const int kq_ld = (tid & 1) * 2;
    const int kk_ld = tid >> 4;
    const int cq_ld = tid & 15;

    for (int k0 = 0; k0 < DD; k0 += 16) {
#pragma unroll
        for (int i = 0; i < 2; i++) {
            float4 v = *(const float4*)&A[(size_t)(bm + r_ld) * DD + k0 + (kq_ld + i) * 4];
            As[(kq_ld + i) * 4 + 0][r_ld] = v.x;
            As[(kq_ld + i) * 4 + 1][r_ld] = v.y;
            As[(kq_ld + i) * 4 + 2][r_ld] = v.z;
            As[(kq_ld + i) * 4 + 3][r_ld] = v.w;
        }
        {
            float4 v = *(const float4*)&W[(size_t)(k0 + kk_ld) * HH + bn + cq_ld * 4];
            *(float4*)&Bs[kk_ld][cq_ld * 4] = v;
        }
        __syncthreads();

#pragma unroll
        for (int kk = 0; kk < 16; kk++) {
            ulonglong2 a0 = *(const ulonglong2*)&As[kk][ty * 8];
            ulonglong2 a1 = *(const ulonglong2*)&As[kk][ty * 8 + 4];
            float4 bq = *(const float4*)&Bs[kk][tx * 4];
            ull b0 = pack2(bq.x, bq.x);
            ull b1 = pack2(bq.y, bq.y);
            ull b2 = pack2(bq.z, bq.z);
            ull b3 = pack2(bq.w, bq.w);
            ull av[4] = {a0.x, a0.y, a1.x, a1.y};
#pragma unroll
            for (int p = 0; p < 4; p++) {
                acc[p][0] = fma2(av[p], b0, acc[p][0]);
                acc[p][1] = fma2(av[p], b1, acc[p][1]);
                acc[p][2] = fma2(av[p], b2, acc[p][2]);
                acc[p][3] = fma2(av[p], b3, acc[p][3]);
            }
        }
        __syncthreads();
    }

    float4 bv;
    bv.x = bias[bn + tx * 4 + 0];
    bv.y = bias[bn + tx * 4 + 1];
    bv.z = bias[bn + tx * 4 + 2];
    bv.w = bias[bn + tx * 4 + 3];
#pragma unroll
    for (int p = 0; p < 4; p++) {
        float lo0, hi0, lo1, hi1, lo2, hi2, lo3, hi3;
        unpack2(acc[p][0], lo0, hi0);
        unpack2(acc[p][1], lo1, hi1);
        unpack2(acc[p][2], lo2, hi2);
        unpack2(acc[p][3], lo3, hi3);
        int row0 = bm + ty * 8 + 2 * p;
        float4 o0; o0.x = lo0 + bv.x; o0.y = lo1 + bv.y; o0.z = lo2 + bv.z; o0.w = lo3 + bv.w;
        float4 o1; o1.x = hi0 + bv.x; o1.y = hi1 + bv.y; o1.z = hi2 + bv.z; o1.w = hi3 + bv.w;
        *(float4*)&out[(size_t)row0 * HH + bn + tx * 4] = o0;
        *(float4*)&out[(size_t)(row0 + 1) * HH + bn + tx * 4] = o1;
    }

    // completion protocol: all stores visible (gpu scope) before counting
    __threadfence();
    __syncthreads();
    if (tid == 0) {
        unsigned old = atomicAdd(&g_xpcnt[blockIdx.y], 1u);
        if (old == 15u)
            asm volatile("st.release.gpu.global.b32 [%0], %1;"
                         :: "l"(&g_xpready[blockIdx.y]), "r"(1u));
    }
}

// ---------------------------------------------------------------------------
// Kernel 2: persistent scan — EXACT R10 structure (256 thr, 8 warps,
// warp = K slice of 128, chunked double-buffered staging, 8r x 2c microtile),
// plus: xp reads gated on g_xpready (xproj runs concurrently).
// ---------------------------------------------------------------------------
__global__ __launch_bounds__(NTHR, 1) void scan_kernel(
    const float* __restrict__ state,   // [64, 1024]
    const float* __restrict__ Whh,     // [1024, 1024]
    float* __restrict__ out,           // d_out
    int write_final)
{
    extern __shared__ float sm[];
    float* wsm    = sm;                        // [1024][32]
    ull*   hstAll = (ull*)(sm + SM_HST);       // 8 warps x 512 u64
    float* red    = sm + SM_RED;               // [8][512]

    const int bid = blockIdx.x;
    const int tid = threadIdx.x;
    const int rq  = bid >> 5;
    const int ct  = bid & 31;

    const int lane = tid & 31;
    const int wid  = tid >> 5;         // = K slice s (8 slices of 128 k)

    const int cg  = lane & 15;         // colpair: cols 2cg, 2cg+1
    const int rg2 = lane >> 4;         // row octet: rows rg2*8 .. +7

    // W slice: wsm[k*32 + c]
    for (int i = tid; i < 1024 * 32; i += NTHR)
        wsm[i] = Whh[(size_t)(i >> 5) * HH + ct * 32 + (i & 31)];

    const int R0 = rq * 16;
    const int k4 = lane & 7;           // float4 index along k
    const int r0 = lane >> 3;          // 0..3: rows r0, r0+4, r0+8, r0+12
    ull* hw = hstAll + wid * 512;      // 2 bufs x 256 u64

    int offA[4], offB[4];
#pragma unroll
    for (int m = 0; m < 4; m++) {
        offA[m] = (((rg2 * 2) ^ m)) * 2;
        offB[m] = (((rg2 * 2 + 1) ^ m)) * 2;
    }
    const int swq = k4 & 3;
    const int q0w = ((r0 >> 1) ^ swq) * 2 + (r0 & 1);
    const int q1w = ((2 + (r0 >> 1)) ^ swq) * 2 + (r0 & 1);

    const int o0 = tid, o1 = tid + 256;
    const int gidx0 = (R0 + (o0 >> 5)) * HH + ct * 32 + (o0 & 31);
    const int gidx1 = (R0 + (o1 >> 5)) * HH + ct * 32 + (o1 & 31);

    unsigned* myslot   = &g_arr[(rq * 32 + ct) * 8];
    const unsigned* po = &g_arr[(rq * 32 + lane) * 8];

    // wait for xp pair 0 before entering the loop
    if (wid == 0) {
        unsigned r;
        do {
            asm volatile("ld.acquire.gpu.global.b32 %0, [%1];"
                         : "=r"(r) : "l"(&g_xpready[0]));
        } while (r == 0u);
    }
    __syncthreads();

    for (int t = 0; t < TT; t++) {
        const float* hsrc = (t == 0) ? state : (out + (size_t)(t - 1) * BB * HH);
        float* xp = out + (size_t)t * BB * HH;

        // xp load at step top — consumed ~4K cyc later in phase 2 (latency hidden)
        float xp0 = __ldcg(&xp[gidx0]);
        float xp1 = __ldcg(&xp[gidx1]);

        ull acc[2][4];
#pragma unroll
        for (int c = 0; c < 2; c++)
#pragma unroll
            for (int j = 0; j < 4; j++) acc[c][j] = 0ull;

        const float* src = &hsrc[(size_t)(R0 + r0) * HH + wid * 128 + k4 * 4];
        float4 vA = __ldcg((const float4*)src);
        float4 vB = __ldcg((const float4*)(src + 4 * HH));
        float4 vC = __ldcg((const float4*)(src + 8 * HH));
        float4 vD = __ldcg((const float4*)(src + 12 * HH));
        int b = 0;

#pragma unroll 1
        for (int ci = 0; ci < 4; ci++) {
            float4 uA, uB, uC, uD;
            if (ci < 3) {   // prefetch next 32-k chunk
                const float* s2 = src + (ci + 1) * 32;
                uA = __ldcg((const float4*)s2);
                uB = __ldcg((const float4*)(s2 + 4 * HH));
                uC = __ldcg((const float4*)(s2 + 8 * HH));
                uD = __ldcg((const float4*)(s2 + 12 * HH));
            }
            // stage current chunk: row pairs (j, j+4) as u64, slot-swizzled
            {
                ull* dst = hw + b * 256;
                float a[4] = {vA.x, vA.y, vA.z, vA.w};
                float bb[4] = {vB.x, vB.y, vB.z, vB.w};
                float c[4] = {vC.x, vC.y, vC.z, vC.w};
                float d[4] = {vD.x, vD.y, vD.z, vD.w};
#pragma unroll
                for (int e = 0; e < 4; e++) {
                    int kb8 = (k4 * 4 + e) * 8;
                    dst[kb8 + q0w] = pack2(a[e], bb[e]);   // rows (r0, r0+4)
                    dst[kb8 + q1w] = pack2(c[e], d[e]);    // rows (r0+8, r0+12)
                }
            }
            __syncwarp();
            // compute chunk: per k: 2 LDS.128 (h) + 1 LDS.64 (w) + 8 FFMA2
            {
                const ull* hb = hw + b * 256;
                const float* wb = &wsm[(wid * 128 + ci * 32) * 32 + 2 * cg];
#pragma unroll
                for (int kk = 0; kk < 32; kk++) {
                    const int m = (kk >> 2) & 3;
                    ulonglong2 hA = *(const ulonglong2*)(hb + kk * 8 + offA[m]);
                    ulonglong2 hB = *(const ulonglong2*)(hb + kk * 8 + offB[m]);
                    float2 wp = *(const float2*)(wb + kk * 32);
                    ull w0 = pack2(wp.x, wp.x);
                    ull w1 = pack2(wp.y, wp.y);
                    acc[0][0] = fma2(hA.x, w0, acc[0][0]);
                    acc[0][1] = fma2(hA.y, w0, acc[0][1]);
                    acc[0][2] = fma2(hB.x, w0, acc[0][2]);
                    acc[0][3] = fma2(hB.y, w0, acc[0][3]);
                    acc[1][0] = fma2(hA.x, w1, acc[1][0]);
                    acc[1][1] = fma2(hA.y, w1, acc[1][1]);
                    acc[1][2] = fma2(hB.x, w1, acc[1][2]);
                    acc[1][3] = fma2(hB.y, w1, acc[1][3]);
                }
            }
            vA = uA; vB = uB; vC = uC; vD = uD;
            b ^= 1;
            __syncwarp();
        }

        // write this warp's 16x32 partial into red[wid][..]
        {
#pragma unroll
            for (int c = 0; c < 2; c++)
#pragma unroll
                for (int j = 0; j < 4; j++) {
                    float lo, hi;
                    unpack2(acc[c][j], lo, hi);
                    red[wid * 512 + (rg2 * 8 + j) * 32 + 2 * cg + c] = lo;
                    red[wid * 512 + (rg2 * 8 + j + 4) * 32 + 2 * cg + c] = hi;
                }
        }
        __syncthreads();

        // phase 2: sum 8 K-slices + xp, tanh, write h_t over xp_t
        {
            float vv0 = xp0, vv1 = xp1;
#pragma unroll
            for (int q = 0; q < 8; q++) {
                vv0 += red[q * 512 + o0];
                vv1 += red[q * 512 + o1];
            }
            float h0 = tanhf(vv0);
            float h1 = tanhf(vv1);
            xp[gidx0] = h0;
            xp[gidx1] = h1;
            if (write_final && t == TT - 1) {
                out[(size_t)TT * BB * HH + gidx0] = h0;
                out[(size_t)TT * BB * HH + gidx1] = h1;
            }
        }

        if (t < TT - 1) {
            __syncthreads();   // all h_t STGs of this block done
            if (tid == 0)
                asm volatile("st.release.gpu.global.b32 [%0], %1;"
                             :: "l"(myslot), "r"((unsigned)(t + 1)));
            if (wid == 0) {            // group h flags
                unsigned v;
                do {
                    asm volatile("ld.acquire.gpu.global.b32 %0, [%1];"
                                 : "=r"(v) : "l"(po));
                } while (!__all_sync(0xffffffffu, v > (unsigned)t));
            } else if (wid == 1) {     // xp readiness for step t+1
                unsigned r;
                do {
                    asm volatile("ld.acquire.gpu.global.b32 %0, [%1];"
                                 : "=r"(r) : "l"(&g_xpready[(t + 1) >> 1]));
                } while (r == 0u);
            }
            __syncthreads();
        }
    }
}

// ---------------------------------------------------------------------------
extern "C" void kernel_launch(void* const* d_in, const int* in_sizes, int n_in,
                              void* d_out, int out_size) {
    const float* inputs = (const float*)d_in[0];   // [T,B,D]
    const float* state  = (const float*)d_in[1];   // [B,H]
    const float* W_xh   = (const float*)d_in[2];   // [D,H]
    const float* W_hh   = (const float*)d_in[3];   // [H,H]
    const float* b_h    = (const float*)d_in[4];   // [H]
    float* out = (float*)d_out;

    int write_final = (out_size >= TT * BB * HH + BB * HH) ? 1 : 0;

    static cudaStream_t s2 = nullptr;
    static cudaEvent_t  eF = nullptr, eJ = nullptr;
    if (!s2) {   // first call is the uncaptured correctness run — safe to create
        cudaStreamCreateWithFlags(&s2, cudaStreamNonBlocking);
        cudaEventCreateWithFlags(&eF, cudaEventDisableTiming);
        cudaEventCreateWithFlags(&eJ, cudaEventDisableTiming);
        cudaFuncSetAttribute(scan_kernel,
                             cudaFuncAttributeMaxDynamicSharedMemorySize,
                             SM_TOT_B);
    }

    // init flags on legacy stream, then fork xproj onto s2, scan stays on legacy
    init_kernel<<<4, 256>>>();
    cudaEventRecord(eF, 0);
    cudaStreamWaitEvent(s2, eF, 0);

    dim3 g1(HH / 64, (TT * BB) / 128);   // (16 col-blocks, 256 t-pairs)
    xproj_kernel<<<g1, 256, 0, s2>>>(inputs, W_xh, b_h, out);
    cudaEventRecord(eJ, s2);

    scan_kernel<<<NBLK, NTHR, SM_TOT_B>>>(state, W_hh, out, write_final);

    cudaStreamWaitEvent(0, eJ, 0);       // join: graph end waits on xproj too
}